// round 6
// baseline (speedup 1.0000x reference)
#include <cuda_runtime.h>
#include <cuda_bf16.h>
#include <math.h>
#include <stdint.h>

#define HWSZ  (256 * 256)
#define NTHR  256
#define NTILES 4096          // 2 x-tiles * 256 rows * 8 batch
#define GRID  152

// ---------------------------------------------------------------------------
// Static device scratch (no cudaMalloc anywhere)
// ---------------------------------------------------------------------------
__device__ uint32_t g_h[(size_t)8 * 200 * HWSZ];          // packed (bf16 hi | bf16 lo)
__device__ __align__(16) unsigned char g_b1[100352];      // L1 weight image (swizzled)
__device__ __align__(16) unsigned char g_b2[93184];       // L2 weight image (swizzled)

// ---------------------------------------------------------------------------
// Swizzled panel addressing: panel = [rows][16 k] bf16 (32B rows).
// 16B chunk of row r, k-half kh lands in bank-group (2r + (kh ^ (r>>2)))%8
// -> every ldmatrix 8-lane phase hits 8 distinct groups (conflict-free).
// ---------------------------------------------------------------------------
__device__ __forceinline__ int swz(int r, int k) {
    return (r >> 3) * 256 + (r & 7) * 32 + ((((k >> 3) ^ (r >> 2)) & 1) << 4) + (k & 7) * 2;
}

__device__ __forceinline__ uint32_t smem_u32(const void* p) {
    uint32_t a;
    asm("{ .reg .u64 t; cvta.to.shared.u64 t, %1; cvt.u32.u64 %0, t; }" : "=r"(a) : "l"(p));
    return a;
}
__device__ __forceinline__ void ldsm_x4(uint32_t* r, uint32_t a) {
    asm volatile("ldmatrix.sync.aligned.m8n8.x4.shared.b16 {%0,%1,%2,%3}, [%4];"
                 : "=r"(r[0]), "=r"(r[1]), "=r"(r[2]), "=r"(r[3]) : "r"(a));
}
__device__ __forceinline__ void ldsm_x2(uint32_t* r, uint32_t a) {
    asm volatile("ldmatrix.sync.aligned.m8n8.x2.shared.b16 {%0,%1}, [%2];"
                 : "=r"(r[0]), "=r"(r[1]) : "r"(a));
}
__device__ __forceinline__ void mma_bf16(float* d, const uint32_t* a, const uint32_t* b) {
    asm volatile(
        "mma.sync.aligned.m16n8k16.row.col.f32.bf16.bf16.f32 "
        "{%0,%1,%2,%3}, {%4,%5,%6,%7}, {%8,%9}, {%0,%1,%2,%3};"
        : "+f"(d[0]), "+f"(d[1]), "+f"(d[2]), "+f"(d[3])
        : "r"(a[0]), "r"(a[1]), "r"(a[2]), "r"(a[3]), "r"(b[0]), "r"(b[1]));
}

__device__ __forceinline__ uint32_t gelu_pack(float v) {
    float g = 0.5f * v * (1.0f + erff(v * 0.70710678118654752440f));
    __nv_bfloat16 h = __float2bfloat16(g);
    __nv_bfloat16 l = __float2bfloat16(g - __bfloat162float(h));
    return (uint32_t)__bfloat16_as_ushort(h) | ((uint32_t)__bfloat16_as_ushort(l) << 16);
}

// ---------------------------------------------------------------------------
// Prep: build swizzled bf16 hi|lo weight panel images in gmem.
// L1: n-pad 224, 224 k-slots (hi 0-111, lo 112-223), panel stride 7168.
// L2: n-pad 112, 416 k-slots (hi 0-207, lo 208-415), panel stride 3584.
// ---------------------------------------------------------------------------
__global__ void prep_w(const float* __restrict__ w1, const float* __restrict__ w2) {
    int tid = blockIdx.x * blockDim.x + threadIdx.x;
    int nth = gridDim.x * blockDim.x;
    for (int i = tid; i < 224 * 224; i += nth) {
        int n = i / 224, s = i - n * 224;
        bool lo = s >= 112;
        int k = lo ? s - 112 : s;
        float v = (n < 200 && k < 100) ? w1[n * 100 + k] : 0.0f;
        __nv_bfloat16 h = __float2bfloat16(v);
        __nv_bfloat16 o = lo ? __float2bfloat16(v - __bfloat162float(h)) : h;
        *(__nv_bfloat16*)(g_b1 + (s >> 4) * 7168 + swz(n, s & 15)) = o;
    }
    for (int i = tid; i < 112 * 416; i += nth) {
        int n = i / 416, s = i - n * 416;
        bool lo = s >= 208;
        int k = lo ? s - 208 : s;
        float v = (n < 100 && k < 200) ? w2[n * 200 + k] : 0.0f;
        __nv_bfloat16 h = __float2bfloat16(v);
        __nv_bfloat16 o = lo ? __float2bfloat16(v - __bfloat162float(h)) : h;
        *(__nv_bfloat16*)(g_b2 + (s >> 4) * 3584 + swz(n, s & 15)) = o;
    }
}

// ---------------------------------------------------------------------------
// Persistent shift-GEMM layer. Per tile: 128 pixels of one (b, y) row.
// A smem: [128 m][2*SEC k-slots] bf16 panels; B smem: weight image.
// D = A @ B^T via mma.sync bf16, fp32 accum, 3 split-terms.
// ---------------------------------------------------------------------------
template<int CK, int GRP, int SEC, int HS, int NOUT, int NPAD, int MWARPS, int MF,
         int OCTD, int ABYTES, int BSTRIDE, int BBYTES, bool L1MODE>
__global__ __launch_bounds__(NTHR, 1) void shift_gemm(
    const void* __restrict__ in_, const unsigned char* __restrict__ bimg,
    const float* __restrict__ bias, void* __restrict__ out_)
{
    constexpr int NWARPS = 8 / MWARPS;
    constexpr int NF = NPAD / (NWARPS * 8);   // 7 for both layers
    constexpr int WM = MF * 16;
    constexpr int WN = NF * 8;
    constexpr int STEPS = 3 * HS;

    extern __shared__ __align__(16) unsigned char smem[];
    const uint32_t sb = smem_u32(smem);
    const int tid = threadIdx.x, wid = tid >> 5, lid = tid & 31;
    const int wm = wid % MWARPS, wn = wid / MWARPS;

    // Copy weight image + zero A region (covers all pad slots once)
    for (int i = tid * 16; i < BBYTES; i += NTHR * 16)
        *(uint4*)(smem + ABYTES + i) = *(const uint4*)(bimg + i);
    for (int i = tid * 16; i < ABYTES; i += NTHR * 16)
        *(uint4*)(smem + i) = make_uint4(0, 0, 0, 0);

    // Per-lane ldmatrix base offsets
    uint32_t aoff[MF];
    {
        int mrow = ((lid >> 3) & 1) * 8 + (lid & 7);
        int kh   = (lid >> 4) & 1;
        #pragma unroll
        for (int mf = 0; mf < MF; mf++)
            aoff[mf] = sb + swz(wm * WM + mf * 16 + mrow, kh * 8);
    }
    uint32_t boff[NF / 2], boff2;
    {
        int nrow = ((lid >> 4) & 1) * 8 + (lid & 7);
        int kh   = (lid >> 3) & 1;
        #pragma unroll
        for (int p = 0; p < NF / 2; p++)
            boff[p] = sb + ABYTES + swz(wn * WN + p * 16 + nrow, kh * 8);
        boff2 = sb + ABYTES + swz(wn * WN + (NF / 2) * 16 + (lid & 7), kh * 8);
    }

    for (int t = blockIdx.x; t < NTILES; t += gridDim.x) {
        const int x0 = (t & 1) << 7;
        const int y  = (t >> 1) & 255;
        const int b  = t >> 9;

        // ---- A fill: shifted load, hi/lo bf16, swizzled STS.128 ----
        for (int i = tid; i < OCTD * 128; i += NTHR) {
            const int oct = i >> 7, pix = i & 127;
            uint32_t hv[4] = {0, 0, 0, 0}, lv[4] = {0, 0, 0, 0};
            #pragma unroll
            for (int j = 0; j < 8; j++) {
                int k = oct * 8 + j;
                uint32_t hb = 0, lb = 0;
                if (k < CK) {
                    int g  = k / GRP;
                    int yy = y + (g == 2) - (g == 3);
                    int xx = x0 + pix + (g == 0) - (g == 1);
                    if ((unsigned)yy < 256u && (unsigned)xx < 256u) {
                        if (L1MODE) {
                            float v = ((const float*)in_)[(((size_t)b * CK + k) * 256 + yy) * 256 + xx];
                            __nv_bfloat16 h = __float2bfloat16(v);
                            hb = __bfloat16_as_ushort(h);
                            lb = __bfloat16_as_ushort(__float2bfloat16(v - __bfloat162float(h)));
                        } else {
                            uint32_t u = ((const uint32_t*)in_)[(((size_t)b * CK + k) * 256 + yy) * 256 + xx];
                            hb = u & 0xFFFFu;
                            lb = u >> 16;
                        }
                    }
                }
                hv[j >> 1] |= hb << ((j & 1) * 16);
                lv[j >> 1] |= lb << ((j & 1) * 16);
            }
            const int kh = oct * 8, kl = SEC + oct * 8;
            *(uint4*)(smem + (kh >> 4) * 4096 + swz(pix, kh & 15)) = make_uint4(hv[0], hv[1], hv[2], hv[3]);
            *(uint4*)(smem + (kl >> 4) * 4096 + swz(pix, kl & 15)) = make_uint4(lv[0], lv[1], lv[2], lv[3]);
        }
        __syncthreads();

        // ---- MMA mainloop ----
        float acc[MF][NF][4];
        #pragma unroll
        for (int mf = 0; mf < MF; mf++)
            #pragma unroll
            for (int nf = 0; nf < NF; nf++)
                #pragma unroll
                for (int q = 0; q < 4; q++) acc[mf][nf][q] = 0.0f;

        #pragma unroll 1
        for (int s = 0; s < STEPS; s++) {
            int as, bs;
            if (s < HS)            { as = s;          bs = s;      }
            else if (s < 2 * HS)   { as = s;          bs = s - HS; }  // lo(x)*hi(w)
            else                   { as = s - 2 * HS; bs = s - HS; }  // hi(x)*lo(w)
            const uint32_t ap = (uint32_t)(as * 4096);
            const uint32_t bp = (uint32_t)(bs * BSTRIDE);

            uint32_t a[MF][4], bf[NF][2];
            #pragma unroll
            for (int mf = 0; mf < MF; mf++) ldsm_x4(a[mf], aoff[mf] + ap);
            #pragma unroll
            for (int p = 0; p < NF / 2; p++) {
                uint32_t r[4];
                ldsm_x4(r, boff[p] + bp);
                bf[2 * p][0] = r[0]; bf[2 * p][1] = r[1];
                bf[2 * p + 1][0] = r[2]; bf[2 * p + 1][1] = r[3];
            }
            if (NF & 1) ldsm_x2(bf[NF - 1], boff2 + bp);

            #pragma unroll
            for (int mf = 0; mf < MF; mf++)
                #pragma unroll
                for (int nf = 0; nf < NF; nf++)
                    mma_bf16(acc[mf][nf], a[mf], bf[nf]);
        }

        // ---- Epilogue ----
        {
            const int r  = lid >> 2;
            const int ci = lid & 3;
            #pragma unroll
            for (int nf = 0; nf < NF; nf++) {
                const int o0 = wn * WN + nf * 8 + ci * 2;
                if (o0 < NOUT) {
                    const float bi0 = __ldg(bias + o0);
                    const float bi1 = __ldg(bias + o0 + 1);
                    #pragma unroll
                    for (int mf = 0; mf < MF; mf++) {
                        const int xg = x0 + wm * WM + mf * 16 + r;
                        const size_t p0 = (((size_t)b * NOUT + o0) * 256 + y) * 256 + xg;
                        const size_t p1 = p0 + HWSZ;   // o0+1
                        const float* d = acc[mf][nf];
                        if (L1MODE) {
                            ((uint32_t*)out_)[p0]     = gelu_pack(d[0] + bi0);
                            ((uint32_t*)out_)[p1]     = gelu_pack(d[1] + bi1);
                            ((uint32_t*)out_)[p0 + 8] = gelu_pack(d[2] + bi0);
                            ((uint32_t*)out_)[p1 + 8] = gelu_pack(d[3] + bi1);
                        } else {
                            ((float*)out_)[p0]     = d[0] + bi0;
                            ((float*)out_)[p1]     = d[1] + bi1;
                            ((float*)out_)[p0 + 8] = d[2] + bi0;
                            ((float*)out_)[p1 + 8] = d[3] + bi1;
                        }
                    }
                }
            }
        }
        __syncthreads();   // protect A smem before next tile's fill
    }
}

// L1: CK=100 GRP=20 SEC=112 HS=7  NOUT=200 NPAD=224 MWARPS=2 MF=4 OCTD=13
//     ABYTES=14*4096=57344  BSTRIDE=7168 BBYTES=100352
// L2: CK=200 GRP=40 SEC=208 HS=13 NOUT=100 NPAD=112 MWARPS=4 MF=2 OCTD=25
//     ABYTES=26*4096=106496 BSTRIDE=3584 BBYTES=93184
static constexpr int SMEM1 = 57344 + 100352;   // 157696
static constexpr int SMEM2 = 106496 + 93184;   // 199680

extern "C" void kernel_launch(void* const* d_in, const int* in_sizes, int n_in,
                              void* d_out, int out_size)
{
    const float* x  = (const float*)d_in[0];
    const float* w1 = (const float*)d_in[1];
    const float* b1 = (const float*)d_in[2];
    const float* w2 = (const float*)d_in[3];
    const float* b2 = (const float*)d_in[4];

    uint32_t* hptr; unsigned char* b1i; unsigned char* b2i;
    cudaGetSymbolAddress((void**)&hptr, g_h);
    cudaGetSymbolAddress((void**)&b1i, g_b1);
    cudaGetSymbolAddress((void**)&b2i, g_b2);

    auto k1 = shift_gemm<100, 20, 112,  7, 200, 224, 2, 4, 13,  57344, 7168, 100352, true >;
    auto k2 = shift_gemm<200, 40, 208, 13, 100, 112, 4, 2, 25, 106496, 3584,  93184, false>;
    cudaFuncSetAttribute(k1, cudaFuncAttributeMaxDynamicSharedMemorySize, SMEM1);
    cudaFuncSetAttribute(k2, cudaFuncAttributeMaxDynamicSharedMemorySize, SMEM2);

    prep_w<<<64, 256>>>(w1, w2);
    k1<<<GRID, NTHR, SMEM1>>>(x, b1i, b1, hptr);
    k2<<<GRID, NTHR, SMEM2>>>(hptr, b2i, b2, (float*)d_out);
}

// round 7
// speedup vs baseline: 2.7893x; 2.7893x over previous
#include <cuda_runtime.h>
#include <cuda_fp16.h>
#include <math.h>
#include <stdint.h>

#define NTHR   256
#define GRID   152
#define NTILES 4096          // 2 x-tiles * 256 rows * 8 batch
#define HW     65536

// ---------------------------------------------------------------------------
// Static device scratch. Planes are PRE-SHIFTED per channel group, so GEMM
// A-fills are plain aligned row copies (cp.async-able).
// ---------------------------------------------------------------------------
__device__ __half g_xh[(size_t)8 * 100 * HW];   // shifted x, fp16 hi
__device__ __half g_xl[(size_t)8 * 100 * HW];   // shifted x, fp16 lo
__device__ __half g_hh[(size_t)8 * 200 * HW];   // shifted gelu(h), fp16 hi
__device__ __half g_hl[(size_t)8 * 200 * HW];   // shifted gelu(h), fp16 lo
__device__ __align__(16) __half g_w1i[224 * 112];   // L1 weight image (50176 B)
__device__ __align__(16) __half g_w2i[112 * 208];   // L2 weight image (46592 B)

// B-panel swizzle (32B rows of 16 halfs), proven in round 5.
__host__ __device__ __forceinline__ int swz(int r, int k) {
    return (r >> 3) * 256 + (r & 7) * 32 + ((((k >> 3) ^ (r >> 2)) & 1) << 4) + (k & 7) * 2;
}

__device__ __forceinline__ uint32_t smem_u32(const void* p) {
    uint32_t a;
    asm("{ .reg .u64 t; cvta.to.shared.u64 t, %1; cvt.u32.u64 %0, t; }" : "=r"(a) : "l"(p));
    return a;
}
__device__ __forceinline__ void ldsm_x4t(uint32_t* r, uint32_t a) {
    asm volatile("ldmatrix.sync.aligned.m8n8.x4.trans.shared.b16 {%0,%1,%2,%3}, [%4];"
                 : "=r"(r[0]), "=r"(r[1]), "=r"(r[2]), "=r"(r[3]) : "r"(a));
}
__device__ __forceinline__ void ldsm_x4(uint32_t* r, uint32_t a) {
    asm volatile("ldmatrix.sync.aligned.m8n8.x4.shared.b16 {%0,%1,%2,%3}, [%4];"
                 : "=r"(r[0]), "=r"(r[1]), "=r"(r[2]), "=r"(r[3]) : "r"(a));
}
__device__ __forceinline__ void ldsm_x2(uint32_t* r, uint32_t a) {
    asm volatile("ldmatrix.sync.aligned.m8n8.x2.shared.b16 {%0,%1}, [%2];"
                 : "=r"(r[0]), "=r"(r[1]) : "r"(a));
}
__device__ __forceinline__ void mma_f16(float* d, const uint32_t* a, const uint32_t* b) {
    asm volatile(
        "mma.sync.aligned.m16n8k16.row.col.f32.f16.f16.f32 "
        "{%0,%1,%2,%3}, {%4,%5,%6,%7}, {%8,%9}, {%0,%1,%2,%3};"
        : "+f"(d[0]), "+f"(d[1]), "+f"(d[2]), "+f"(d[3])
        : "r"(a[0]), "r"(a[1]), "r"(a[2]), "r"(a[3]), "r"(b[0]), "r"(b[1]));
}
#define CP_ASYNC16(dst, src, sz) \
    asm volatile("cp.async.cg.shared.global [%0], [%1], 16, %2;" \
                 :: "r"(dst), "l"(src), "r"(sz))
#define CP_COMMIT()  asm volatile("cp.async.commit_group;" ::: "memory")
#define CP_WAIT0()   asm volatile("cp.async.wait_group 0;" ::: "memory")

// ---------------------------------------------------------------------------
// prep_x: build shifted fp16 hi/lo planes from fp32 x. Two pixels per thread.
// groups of 20 channels: +x, -x, +y, -y, identity.
// ---------------------------------------------------------------------------
__global__ void prep_x(const float* __restrict__ x) {
    size_t i = (size_t)blockIdx.x * NTHR + threadIdx.x;
    if (i >= (size_t)8 * 100 * HW / 2) return;
    const int x2 = (int)(i & 127) * 2;
    const int y  = (int)(i >> 7) & 255;
    const int cb = (int)(i >> 15);           // b*100 + c
    const int c  = cb % 100;
    const int g  = c / 20;
    const int dy = (g == 2) - (g == 3);
    const int dx = (g == 0) - (g == 1);
    const int sy = y + dy;
    const float* row = x + (((size_t)cb) << 16) + (size_t)sy * 256;
    uint32_t hv = 0, lv = 0;
    #pragma unroll
    for (int j = 0; j < 2; j++) {
        int sx = x2 + j + dx;
        float v = ((unsigned)sy < 256u && (unsigned)sx < 256u) ? row[sx] : 0.0f;
        __half hh = __float2half_rn(v);
        __half hl = __float2half_rn(v - __half2float(hh));
        hv |= (uint32_t)__half_as_ushort(hh) << (16 * j);
        lv |= (uint32_t)__half_as_ushort(hl) << (16 * j);
    }
    size_t o = (((size_t)cb) << 16) + (size_t)y * 256 + x2;
    *(uint32_t*)(g_xh + o) = hv;
    *(uint32_t*)(g_xl + o) = lv;
}

// prep_w: fp16 swizzled weight panel images (zero-padded).
__global__ void prep_w(const float* __restrict__ w1, const float* __restrict__ w2) {
    int tid = blockIdx.x * blockDim.x + threadIdx.x;
    int nth = gridDim.x * blockDim.x;
    for (int i = tid; i < 224 * 112; i += nth) {
        int n = i / 112, k = i - n * 112;
        float v = (n < 200 && k < 100) ? w1[n * 100 + k] : 0.0f;
        *(__half*)((char*)g_w1i + (k >> 4) * 7168 + swz(n, k & 15)) = __float2half_rn(v);
    }
    for (int i = tid; i < 112 * 208; i += nth) {
        int n = i / 208, k = i - n * 208;
        float v = (n < 100 && k < 200) ? w2[n * 200 + k] : 0.0f;
        *(__half*)((char*)g_w2i + (k >> 4) * 3584 + swz(n, k & 15)) = __float2half_rn(v);
    }
}

// ---------------------------------------------------------------------------
// Persistent shift-GEMM. Tile = 128 pixels of one (b, y) row.
// A smem: [2*SECS k-slots][128 pix fp16] rows (256B), chunk-XOR swizzled,
//         filled by cp.async, read via ldmatrix.x4.trans.
// B smem: weight image, read via ldmatrix (non-trans), as round 5.
// 2 terms: (x_hi + x_lo) @ w_fp16, fp32 accumulate.
// ---------------------------------------------------------------------------
template<int CK, int SECS, int STEPS, int NOUT, int NPAD, int MWARPS, int MF,
         int BPANEL, int BBYTES, bool L1M>
__global__ __launch_bounds__(NTHR, 1) void shift_gemm(
    const __half* __restrict__ ph, const __half* __restrict__ pl,
    const __half* __restrict__ bimg, const float* __restrict__ bias,
    float* __restrict__ out_)
{
    constexpr int NF = NPAD / ((8 / MWARPS) * 8);    // 7 both layers
    constexpr int WM = MF * 16;
    constexpr int WN = NF * 8;
    constexpr int ABYTES = 2 * SECS * 256;
    constexpr int HSTEP = STEPS / 2;

    extern __shared__ __align__(16) unsigned char smem[];
    const uint32_t sbA = smem_u32(smem);
    const uint32_t sbB = sbA + ABYTES;
    const int tid = threadIdx.x, wid = tid >> 5, lid = tid & 31;
    const int wm = wid % MWARPS, wn = wid / MWARPS;

    // Copy B image to smem (once)
    for (int i = tid * 16; i < BBYTES; i += NTHR * 16)
        *(uint4*)(smem + ABYTES + i) = *(const uint4*)((const char*)bimg + i);

    // A-fill: cp.async whole tile (shift already baked into planes)
    auto fill = [&](int t) {
        const int x0 = (t & 1) << 7;
        const int y  = (t >> 1) & 255;
        const int b  = t >> 9;
        const size_t pbase = (((size_t)b * CK) << 16) + (size_t)y * 256 + x0;
        for (int j = tid; j < 2 * SECS * 16; j += NTHR) {
            const int s = j >> 4, c = j & 15;
            const int sec = (s >= SECS);
            const int kk  = s - (sec ? SECS : 0);
            const __half* src = (sec ? pl : ph) + pbase + (((size_t)kk) << 16) + c * 8;
            const uint32_t dst = sbA + s * 256 + (((c ^ (s & 7)) & 15) << 4);
            const int sz = (kk < CK) ? 16 : 0;
            CP_ASYNC16(dst, src, sz);
        }
        CP_COMMIT();
    };

    // ldmatrix lane bases
    const int lg = lid >> 3, lr = lid & 7;
    uint32_t aoff[MF];
    #pragma unroll
    for (int mf = 0; mf < MF; mf++) {
        const int m0 = wm * WM + mf * 16 + (lg & 1) * 8;
        aoff[mf] = sbA + (uint32_t)(((lg >> 1) * 8 + lr) * 256)
                 + (uint32_t)((((m0 >> 3) ^ lr) & 15) << 4);
    }
    uint32_t boff[NF / 2], boff2;
    {
        const int nrow = ((lid >> 4) & 1) * 8 + (lid & 7);
        const int kh   = (lid >> 3) & 1;
        #pragma unroll
        for (int p = 0; p < NF / 2; p++)
            boff[p] = sbB + swz(wn * WN + p * 16 + nrow, kh * 8);
        boff2 = sbB + swz(wn * WN + (NF / 2) * 16 + (lid & 7), kh * 8);
    }

    // Prologue: fill first tile
    if (blockIdx.x < NTILES) fill(blockIdx.x);
    CP_WAIT0();
    __syncthreads();

    for (int t = blockIdx.x; t < NTILES; t += GRID) {
        const int x0 = (t & 1) << 7;
        const int y  = (t >> 1) & 255;
        const int b  = t >> 9;

        // ---- MMA mainloop ----
        float acc[MF][NF][4];
        #pragma unroll
        for (int mf = 0; mf < MF; mf++)
            #pragma unroll
            for (int nf = 0; nf < NF; nf++)
                #pragma unroll
                for (int q = 0; q < 4; q++) acc[mf][nf][q] = 0.0f;

        #pragma unroll 2
        for (int s = 0; s < STEPS; s++) {
            const uint32_t ap = (uint32_t)s * 4096;
            const int sb2 = (s >= HSTEP) ? s - HSTEP : s;
            const uint32_t bp = (uint32_t)sb2 * BPANEL;

            uint32_t a[MF][4], bf[NF][2];
            #pragma unroll
            for (int mf = 0; mf < MF; mf++) ldsm_x4t(a[mf], aoff[mf] + ap);
            #pragma unroll
            for (int p = 0; p < NF / 2; p++) {
                uint32_t r[4];
                ldsm_x4(r, boff[p] + bp);
                bf[2 * p][0] = r[0]; bf[2 * p][1] = r[1];
                bf[2 * p + 1][0] = r[2]; bf[2 * p + 1][1] = r[3];
            }
            if (NF & 1) ldsm_x2(bf[NF - 1], boff2 + bp);

            #pragma unroll
            for (int mf = 0; mf < MF; mf++)
                #pragma unroll
                for (int nf = 0; nf < NF; nf++)
                    mma_f16(acc[mf][nf], a[mf], bf[nf]);
        }
        __syncthreads();              // all warps done reading A

        // ---- Prefetch next tile's A while epilogue runs ----
        if (t + GRID < NTILES) fill(t + GRID);

        // ---- Epilogue ----
        const int r  = lid >> 2;
        const int ci = lid & 3;
        #pragma unroll
        for (int nf = 0; nf < NF; nf++) {
            const int o0 = wn * WN + nf * 8 + ci * 2;
            if (o0 < NOUT) {
                const float bi0 = __ldg(bias + o0);
                const float bi1 = __ldg(bias + o0 + 1);
                #pragma unroll
                for (int mf = 0; mf < MF; mf++) {
                    const float* d = acc[mf][nf];
                    #pragma unroll
                    for (int q = 0; q < 4; q++) {
                        const int o  = o0 + (q & 1);
                        const int xg = x0 + wm * WM + mf * 16 + r + (q >> 1) * 8;
                        float v = d[q] + ((q & 1) ? bi1 : bi0);
                        if (L1M) {
                            // exact gelu, split, store into SHIFTED position
                            v = 0.5f * v * (1.0f + erff(v * 0.70710678118654752440f));
                            __half hh = __float2half_rn(v);
                            __half hl = __float2half_rn(v - __half2float(hh));
                            const int g  = o / 40;
                            const int dx = (g == 0) - (g == 1);
                            const int dy = (g == 2) - (g == 3);
                            const int tx = xg - dx, ty = y - dy;
                            const size_t base = ((size_t)(b * 200 + o)) << 16;
                            if ((unsigned)tx < 256u && (unsigned)ty < 256u) {
                                g_hh[base + (size_t)ty * 256 + tx] = hh;
                                g_hl[base + (size_t)ty * 256 + tx] = hl;
                            }
                            const bool zx = (dx == 1 && xg == 255) || (dx == -1 && xg == 0);
                            const bool zy = (dy == 1 && y == 255) || (dy == -1 && y == 0);
                            if (zx || zy) {
                                g_hh[base + (size_t)y * 256 + xg] = __ushort_as_half(0);
                                g_hl[base + (size_t)y * 256 + xg] = __ushort_as_half(0);
                            }
                        } else {
                            out_[(((size_t)(b * NOUT + o)) << 16) + (size_t)y * 256 + xg] = v;
                        }
                    }
                }
            }
        }

        CP_WAIT0();                   // next tile's A landed
        __syncthreads();
    }
}

// L1: CK=100 SECS=112 STEPS=14 NOUT=200 NPAD=224 MWARPS=2 MF=4 BPANEL=7168 BBYTES=50176
// L2: CK=200 SECS=208 STEPS=26 NOUT=100 NPAD=112 MWARPS=4 MF=2 BPANEL=3584 BBYTES=46592
static constexpr int SMEM1 = 2 * 112 * 256 + 50176;   // 107520
static constexpr int SMEM2 = 2 * 208 * 256 + 46592;   // 153088

extern "C" void kernel_launch(void* const* d_in, const int* in_sizes, int n_in,
                              void* d_out, int out_size)
{
    const float* x  = (const float*)d_in[0];
    const float* w1 = (const float*)d_in[1];
    const float* b1 = (const float*)d_in[2];
    const float* w2 = (const float*)d_in[3];
    const float* b2 = (const float*)d_in[4];

    __half *xh, *xl, *hh, *hl, *w1i, *w2i;
    cudaGetSymbolAddress((void**)&xh, g_xh);
    cudaGetSymbolAddress((void**)&xl, g_xl);
    cudaGetSymbolAddress((void**)&hh, g_hh);
    cudaGetSymbolAddress((void**)&hl, g_hl);
    cudaGetSymbolAddress((void**)&w1i, g_w1i);
    cudaGetSymbolAddress((void**)&w2i, g_w2i);

    auto k1 = shift_gemm<100, 112, 14, 200, 224, 2, 4, 7168, 50176, true >;
    auto k2 = shift_gemm<200, 208, 26, 100, 112, 4, 2, 3584, 46592, false>;
    cudaFuncSetAttribute(k1, cudaFuncAttributeMaxDynamicSharedMemorySize, SMEM1);
    cudaFuncSetAttribute(k2, cudaFuncAttributeMaxDynamicSharedMemorySize, SMEM2);

    prep_x<<<(int)(((size_t)8 * 100 * HW / 2 + NTHR - 1) / NTHR), NTHR>>>(x);
    prep_w<<<64, 256>>>(w1, w2);
    k1<<<GRID, NTHR, SMEM1>>>(xh, xl, w1i, b1, nullptr);
    k2<<<GRID, NTHR, SMEM2>>>(hh, hl, w2i, b2, (float*)d_out);
}

// round 9
// speedup vs baseline: 3.6919x; 1.3236x over previous
#include <cuda_runtime.h>
#include <cuda_fp16.h>
#include <math.h>
#include <stdint.h>

#define NTHR   256
#define GRID   304           // 2 CTAs/SM * 152 SMs
#define NTILES 4096          // 2 x-tiles * 256 rows * 8 batch
#define HW     65536

// ---------------------------------------------------------------------------
// Static device scratch. Planes are PRE-SHIFTED per channel group, so GEMM
// A-fills are plain aligned row copies (cp.async-able). Single fp16 precision
// (measured: w-rounding alone gives 2.46e-4; x+h rounding adds ~2.8e-4 RMS
// each in quadrature -> ~5e-4 total, 2x margin under the 1e-3 gate).
// ---------------------------------------------------------------------------
__device__ __half g_xs[(size_t)8 * 100 * HW];   // shifted x, fp16
__device__ __half g_hs[(size_t)8 * 200 * HW];   // shifted gelu(h), fp16
__device__ __align__(16) __half g_w1i[224 * 112];   // L1 weight image (50176 B)
__device__ __align__(16) __half g_w2i[112 * 208];   // L2 weight image (46592 B)

// B-panel swizzle (32B rows of 16 halfs), proven in rounds 5-6.
__host__ __device__ __forceinline__ int swz(int r, int k) {
    return (r >> 3) * 256 + (r & 7) * 32 + ((((k >> 3) ^ (r >> 2)) & 1) << 4) + (k & 7) * 2;
}

__device__ __forceinline__ uint32_t smem_u32(const void* p) {
    uint32_t a;
    asm("{ .reg .u64 t; cvta.to.shared.u64 t, %1; cvt.u32.u64 %0, t; }" : "=r"(a) : "l"(p));
    return a;
}
__device__ __forceinline__ void ldsm_x4t(uint32_t* r, uint32_t a) {
    asm volatile("ldmatrix.sync.aligned.m8n8.x4.trans.shared.b16 {%0,%1,%2,%3}, [%4];"
                 : "=r"(r[0]), "=r"(r[1]), "=r"(r[2]), "=r"(r[3]) : "r"(a));
}
__device__ __forceinline__ void ldsm_x4(uint32_t* r, uint32_t a) {
    asm volatile("ldmatrix.sync.aligned.m8n8.x4.shared.b16 {%0,%1,%2,%3}, [%4];"
                 : "=r"(r[0]), "=r"(r[1]), "=r"(r[2]), "=r"(r[3]) : "r"(a));
}
__device__ __forceinline__ void ldsm_x2(uint32_t* r, uint32_t a) {
    asm volatile("ldmatrix.sync.aligned.m8n8.x2.shared.b16 {%0,%1}, [%2];"
                 : "=r"(r[0]), "=r"(r[1]) : "r"(a));
}
__device__ __forceinline__ void mma_f16(float* d, const uint32_t* a, const uint32_t* b) {
    asm volatile(
        "mma.sync.aligned.m16n8k16.row.col.f32.f16.f16.f32 "
        "{%0,%1,%2,%3}, {%4,%5,%6,%7}, {%8,%9}, {%0,%1,%2,%3};"
        : "+f"(d[0]), "+f"(d[1]), "+f"(d[2]), "+f"(d[3])
        : "r"(a[0]), "r"(a[1]), "r"(a[2]), "r"(a[3]), "r"(b[0]), "r"(b[1]));
}
#define CP_ASYNC16(dst, src, sz) \
    asm volatile("cp.async.cg.shared.global [%0], [%1], 16, %2;" \
                 :: "r"(dst), "l"(src), "r"(sz))
#define CP_COMMIT()  asm volatile("cp.async.commit_group;" ::: "memory")
#define CP_WAIT0()   asm volatile("cp.async.wait_group 0;" ::: "memory")

// ---------------------------------------------------------------------------
// prep_x: build shifted fp16 plane from fp32 x. Four pixels per thread.
// groups of 20 channels: +x, -x, +y, -y, identity.
// ---------------------------------------------------------------------------
__global__ void prep_x(const float* __restrict__ x) {
    size_t i = (size_t)blockIdx.x * NTHR + threadIdx.x;
    if (i >= (size_t)8 * 100 * HW / 4) return;
    const int x4 = (int)(i & 63) * 4;
    const int y  = (int)(i >> 6) & 255;
    const int cb = (int)(i >> 14);           // b*100 + c
    const int c  = cb % 100;
    const int g  = c / 20;
    const int dy = (g == 2) - (g == 3);
    const int dx = (g == 0) - (g == 1);
    const int sy = y + dy;
    const float* row = x + (((size_t)cb) << 16) + (size_t)sy * 256;
    uint32_t v01 = 0, v23 = 0;
    #pragma unroll
    for (int j = 0; j < 4; j++) {
        int sx = x4 + j + dx;
        float v = ((unsigned)sy < 256u && (unsigned)sx < 256u) ? row[sx] : 0.0f;
        uint32_t h = __half_as_ushort(__float2half_rn(v));
        if (j < 2) v01 |= h << (16 * j); else v23 |= h << (16 * (j - 2));
    }
    size_t o = (((size_t)cb) << 16) + (size_t)y * 256 + x4;
    *(uint2*)(g_xs + o) = make_uint2(v01, v23);
}

// prep_w: fp16 swizzled weight panel images (zero-padded).
__global__ void prep_w(const float* __restrict__ w1, const float* __restrict__ w2) {
    int tid = blockIdx.x * blockDim.x + threadIdx.x;
    int nth = gridDim.x * blockDim.x;
    for (int i = tid; i < 224 * 112; i += nth) {
        int n = i / 112, k = i - n * 112;
        float v = (n < 200 && k < 100) ? w1[n * 100 + k] : 0.0f;
        *(__half*)((char*)g_w1i + (k >> 4) * 7168 + swz(n, k & 15)) = __float2half_rn(v);
    }
    for (int i = tid; i < 112 * 208; i += nth) {
        int n = i / 208, k = i - n * 208;
        float v = (n < 100 && k < 200) ? w2[n * 200 + k] : 0.0f;
        *(__half*)((char*)g_w2i + (k >> 4) * 3584 + swz(n, k & 15)) = __float2half_rn(v);
    }
}

// ---------------------------------------------------------------------------
// Persistent shift-GEMM. Tile = 128 pixels of one (b, y) row.
// A smem: [SECS k-slots][128 pix fp16] rows (256B), chunk-XOR swizzled,
//         filled by cp.async (pad slots zero-filled via src-size 0),
//         read via ldmatrix.x4.trans.
// B smem: weight image, read via ldmatrix (non-trans).
// ---------------------------------------------------------------------------
template<int CK, int SECS, int STEPS, int NOUT, int NPAD, int MWARPS, int MF,
         int BPANEL, int BBYTES, bool L1M>
__global__ __launch_bounds__(NTHR, 2) void shift_gemm(
    const __half* __restrict__ ph, const __half* __restrict__ bimg,
    const float* __restrict__ bias, float* __restrict__ out_)
{
    constexpr int NF = NPAD / ((8 / MWARPS) * 8);    // 7 both layers
    constexpr int WM = MF * 16;
    constexpr int WN = NF * 8;
    constexpr int ABYTES = SECS * 256;

    extern __shared__ __align__(16) unsigned char smem[];
    const uint32_t sbA = smem_u32(smem);
    const uint32_t sbB = sbA + ABYTES;
    const int tid = threadIdx.x, wid = tid >> 5, lid = tid & 31;
    const int wm = wid % MWARPS, wn = wid / MWARPS;

    // Copy B image to smem (once)
    for (int i = tid * 16; i < BBYTES; i += NTHR * 16)
        *(uint4*)(smem + ABYTES + i) = *(const uint4*)((const char*)bimg + i);

    // A-fill: cp.async whole tile (shift already baked into the plane)
    auto fill = [&](int t) {
        const int x0 = (t & 1) << 7;
        const int y  = (t >> 1) & 255;
        const int b  = t >> 9;
        const size_t pbase = (((size_t)b * CK) << 16) + (size_t)y * 256 + x0;
        for (int j = tid; j < SECS * 16; j += NTHR) {
            const int s = j >> 4, c = j & 15;
            const __half* src = ph + pbase + (((size_t)s) << 16) + c * 8;
            const uint32_t dst = sbA + s * 256 + (((c ^ (s & 7)) & 15) << 4);
            const int sz = (s < CK) ? 16 : 0;   // pad k-slots -> zero-fill
            CP_ASYNC16(dst, src, sz);
        }
        CP_COMMIT();
    };

    // ldmatrix lane bases
    const int lg = lid >> 3, lr = lid & 7;
    uint32_t aoff[MF];
    #pragma unroll
    for (int mf = 0; mf < MF; mf++) {
        const int m0 = wm * WM + mf * 16 + (lg & 1) * 8;
        aoff[mf] = sbA + (uint32_t)(((lg >> 1) * 8 + lr) * 256)
                 + (uint32_t)((((m0 >> 3) ^ lr) & 15) << 4);
    }
    uint32_t boff[NF / 2], boff2;
    {
        const int nrow = ((lid >> 4) & 1) * 8 + (lid & 7);
        const int kh   = (lid >> 3) & 1;
        #pragma unroll
        for (int p = 0; p < NF / 2; p++)
            boff[p] = sbB + swz(wn * WN + p * 16 + nrow, kh * 8);
        boff2 = sbB + swz(wn * WN + (NF / 2) * 16 + (lid & 7), kh * 8);
    }

    // Prologue: fill first tile
    if ((int)blockIdx.x < NTILES) fill(blockIdx.x);
    CP_WAIT0();
    __syncthreads();

    for (int t = blockIdx.x; t < NTILES; t += GRID) {
        const int x0 = (t & 1) << 7;
        const int y  = (t >> 1) & 255;
        const int b  = t >> 9;

        // ---- MMA mainloop ----
        float acc[MF][NF][4];
        #pragma unroll
        for (int mf = 0; mf < MF; mf++)
            #pragma unroll
            for (int nf = 0; nf < NF; nf++)
                #pragma unroll
                for (int q = 0; q < 4; q++) acc[mf][nf][q] = 0.0f;

        #pragma unroll 2
        for (int s = 0; s < STEPS; s++) {
            const uint32_t ap = (uint32_t)s * 4096;
            const uint32_t bp = (uint32_t)s * BPANEL;

            uint32_t a[MF][4], bf[NF][2];
            #pragma unroll
            for (int mf = 0; mf < MF; mf++) ldsm_x4t(a[mf], aoff[mf] + ap);
            #pragma unroll
            for (int p = 0; p < NF / 2; p++) {
                uint32_t r[4];
                ldsm_x4(r, boff[p] + bp);
                bf[2 * p][0] = r[0]; bf[2 * p][1] = r[1];
                bf[2 * p + 1][0] = r[2]; bf[2 * p + 1][1] = r[3];
            }
            if (NF & 1) ldsm_x2(bf[NF - 1], boff2 + bp);

            #pragma unroll
            for (int mf = 0; mf < MF; mf++)
                #pragma unroll
                for (int nf = 0; nf < NF; nf++)
                    mma_f16(acc[mf][nf], a[mf], bf[nf]);
        }
        __syncthreads();              // all warps done reading A

        // ---- Prefetch next tile's A while epilogue runs ----
        if (t + GRID < NTILES) fill(t + GRID);

        // ---- Epilogue ----
        const int r  = lid >> 2;
        const int ci = lid & 3;
        #pragma unroll
        for (int nf = 0; nf < NF; nf++) {
            const int o0 = wn * WN + nf * 8 + ci * 2;
            if (o0 < NOUT) {
                const float bi0 = __ldg(bias + o0);
                const float bi1 = __ldg(bias + o0 + 1);
                #pragma unroll
                for (int mf = 0; mf < MF; mf++) {
                    const float* d = acc[mf][nf];
                    #pragma unroll
                    for (int q = 0; q < 4; q++) {
                        const int o  = o0 + (q & 1);
                        const int xg = x0 + wm * WM + mf * 16 + r + (q >> 1) * 8;
                        float v = d[q] + ((q & 1) ? bi1 : bi0);
                        if (L1M) {
                            // exact gelu, store fp16 into SHIFTED position
                            v = 0.5f * v * (1.0f + erff(v * 0.70710678118654752440f));
                            const __half hv = __float2half_rn(v);
                            const int g  = o / 40;
                            const int dx = (g == 0) - (g == 1);
                            const int dy = (g == 2) - (g == 3);
                            const int tx = xg - dx, ty = y - dy;
                            const size_t base = ((size_t)(b * 200 + o)) << 16;
                            if ((unsigned)tx < 256u && (unsigned)ty < 256u)
                                g_hs[base + (size_t)ty * 256 + tx] = hv;
                            const bool zx = (dx == 1 && xg == 255) || (dx == -1 && xg == 0);
                            const bool zy = (dy == 1 && y == 255) || (dy == -1 && y == 0);
                            if (zx || zy)
                                g_hs[base + (size_t)y * 256 + xg] = __ushort_as_half(0);
                        } else {
                            out_[(((size_t)(b * NOUT + o)) << 16) + (size_t)y * 256 + xg] = v;
                        }
                    }
                }
            }
        }

        CP_WAIT0();                   // next tile's A landed
        __syncthreads();
    }
}

// L1: CK=100 SECS=112 STEPS=7  NOUT=200 NPAD=224 MWARPS=2 MF=4 BPANEL=7168 BBYTES=50176
// L2: CK=200 SECS=208 STEPS=13 NOUT=100 NPAD=112 MWARPS=4 MF=2 BPANEL=3584 BBYTES=46592
static constexpr int SMEM1 = 112 * 256 + 50176;   // 78848  (2 CTAs/SM)
static constexpr int SMEM2 = 208 * 256 + 46592;   // 99840  (2 CTAs/SM)

extern "C" void kernel_launch(void* const* d_in, const int* in_sizes, int n_in,
                              void* d_out, int out_size)
{
    const float* x  = (const float*)d_in[0];
    const float* w1 = (const float*)d_in[1];
    const float* b1 = (const float*)d_in[2];
    const float* w2 = (const float*)d_in[3];
    const float* b2 = (const float*)d_in[4];

    __half *xs, *hs, *w1i, *w2i;
    cudaGetSymbolAddress((void**)&xs, g_xs);
    cudaGetSymbolAddress((void**)&hs, g_hs);
    cudaGetSymbolAddress((void**)&w1i, g_w1i);
    cudaGetSymbolAddress((void**)&w2i, g_w2i);

    auto k1 = shift_gemm<100, 112, 7, 200, 224, 2, 4, 7168, 50176, true >;
    auto k2 = shift_gemm<200, 208, 13, 100, 112, 4, 2, 3584, 46592, false>;
    cudaFuncSetAttribute(k1, cudaFuncAttributeMaxDynamicSharedMemorySize, SMEM1);
    cudaFuncSetAttribute(k2, cudaFuncAttributeMaxDynamicSharedMemorySize, SMEM2);

    prep_x<<<(int)(((size_t)8 * 100 * HW / 4 + NTHR - 1) / NTHR), NTHR>>>(x);
    prep_w<<<64, 256>>>(w1, w2);
    k1<<<GRID, NTHR, SMEM1>>>(xs, w1i, b1, nullptr);
    k2<<<GRID, NTHR, SMEM2>>>(hs, w2i, b2, (float*)d_out);
}

// round 11
// speedup vs baseline: 4.6484x; 1.2591x over previous
#include <cuda_runtime.h>
#include <cuda_fp16.h>
#include <math.h>
#include <stdint.h>

#define NTHR   256
#define GRID   304           // 2 CTAs/SM * 152 SMs
#define HW     65536

// ---------------------------------------------------------------------------
// Static device scratch. Planes are PRE-SHIFTED per channel group, so GEMM
// A-fills are plain aligned row copies (cp.async-able). Single fp16 precision
// (measured rel_err 3.5e-4, ~3x margin under the 1e-3 gate).
// ---------------------------------------------------------------------------
__device__ __half g_xs[(size_t)8 * 100 * HW];   // shifted x, fp16
__device__ __half g_hs[(size_t)8 * 200 * HW];   // shifted gelu(h), fp16
__device__ __align__(16) __half g_w1i[224 * 112];   // L1 weight image (50176 B)
__device__ __align__(16) __half g_w2i[112 * 208];   // L2 weight image (46592 B)

// B-panel swizzle (32B rows of 16 halfs), proven in rounds 5-9.
__host__ __device__ __forceinline__ int swz(int r, int k) {
    return (r >> 3) * 256 + (r & 7) * 32 + ((((k >> 3) ^ (r >> 2)) & 1) << 4) + (k & 7) * 2;
}

__device__ __forceinline__ uint32_t smem_u32(const void* p) {
    uint32_t a;
    asm("{ .reg .u64 t; cvta.to.shared.u64 t, %1; cvt.u32.u64 %0, t; }" : "=r"(a) : "l"(p));
    return a;
}
__device__ __forceinline__ void ldsm_x4t(uint32_t* r, uint32_t a) {
    asm volatile("ldmatrix.sync.aligned.m8n8.x4.trans.shared.b16 {%0,%1,%2,%3}, [%4];"
                 : "=r"(r[0]), "=r"(r[1]), "=r"(r[2]), "=r"(r[3]) : "r"(a));
}
__device__ __forceinline__ void ldsm_x4(uint32_t* r, uint32_t a) {
    asm volatile("ldmatrix.sync.aligned.m8n8.x4.shared.b16 {%0,%1,%2,%3}, [%4];"
                 : "=r"(r[0]), "=r"(r[1]), "=r"(r[2]), "=r"(r[3]) : "r"(a));
}
__device__ __forceinline__ void ldsm_x2(uint32_t* r, uint32_t a) {
    asm volatile("ldmatrix.sync.aligned.m8n8.x2.shared.b16 {%0,%1}, [%2];"
                 : "=r"(r[0]), "=r"(r[1]) : "r"(a));
}
__device__ __forceinline__ void mma_f16(float* d, const uint32_t* a, const uint32_t* b) {
    asm volatile(
        "mma.sync.aligned.m16n8k16.row.col.f32.f16.f16.f32 "
        "{%0,%1,%2,%3}, {%4,%5,%6,%7}, {%8,%9}, {%0,%1,%2,%3};"
        : "+f"(d[0]), "+f"(d[1]), "+f"(d[2]), "+f"(d[3])
        : "r"(a[0]), "r"(a[1]), "r"(a[2]), "r"(a[3]), "r"(b[0]), "r"(b[1]));
}
#define CP_ASYNC16(dst, src, sz) \
    asm volatile("cp.async.cg.shared.global [%0], [%1], 16, %2;" \
                 :: "r"(dst), "l"(src), "r"(sz))
#define CP_COMMIT()  asm volatile("cp.async.commit_group;" ::: "memory")
#define CP_WAIT0()   asm volatile("cp.async.wait_group 0;" ::: "memory")

// ---------------------------------------------------------------------------
// prep_x: build shifted fp16 plane from fp32 x. Four pixels per thread.
// groups of 20 channels: +x, -x, +y, -y, identity.
// ---------------------------------------------------------------------------
__global__ void prep_x(const float* __restrict__ x) {
    size_t i = (size_t)blockIdx.x * NTHR + threadIdx.x;
    if (i >= (size_t)8 * 100 * HW / 4) return;
    const int x4 = (int)(i & 63) * 4;
    const int y  = (int)(i >> 6) & 255;
    const int cb = (int)(i >> 14);           // b*100 + c
    const int c  = cb % 100;
    const int g  = c / 20;
    const int dy = (g == 2) - (g == 3);
    const int dx = (g == 0) - (g == 1);
    const int sy = y + dy;
    const float* row = x + (((size_t)cb) << 16) + (size_t)sy * 256;
    uint32_t v01 = 0, v23 = 0;
    #pragma unroll
    for (int j = 0; j < 4; j++) {
        int sx = x4 + j + dx;
        float v = ((unsigned)sy < 256u && (unsigned)sx < 256u) ? row[sx] : 0.0f;
        uint32_t h = __half_as_ushort(__float2half_rn(v));
        if (j < 2) v01 |= h << (16 * j); else v23 |= h << (16 * (j - 2));
    }
    size_t o = (((size_t)cb) << 16) + (size_t)y * 256 + x4;
    *(uint2*)(g_xs + o) = make_uint2(v01, v23);
}

// prep_w: fp16 swizzled weight panel images (zero-padded).
__global__ void prep_w(const float* __restrict__ w1, const float* __restrict__ w2) {
    int tid = blockIdx.x * blockDim.x + threadIdx.x;
    int nth = gridDim.x * blockDim.x;
    for (int i = tid; i < 224 * 112; i += nth) {
        int n = i / 112, k = i - n * 112;
        float v = (n < 200 && k < 100) ? w1[n * 100 + k] : 0.0f;
        *(__half*)((char*)g_w1i + (k >> 4) * 7168 + swz(n, k & 15)) = __float2half_rn(v);
    }
    for (int i = tid; i < 112 * 208; i += nth) {
        int n = i / 208, k = i - n * 208;
        float v = (n < 100 && k < 200) ? w2[n * 200 + k] : 0.0f;
        *(__half*)((char*)g_w2i + (k >> 4) * 3584 + swz(n, k & 15)) = __float2half_rn(v);
    }
}

// ---------------------------------------------------------------------------
// Persistent shift-GEMM. Tile = MPIX pixels of one (b, y) row.
// A smem: [SECS k-slots][MPIX fp16] rows (MPIX*2 B, NCH 16B chunks),
//         XOR-chunk swizzled, filled by cp.async, read ldmatrix.x4.trans.
// B smem: weight image, read via ldmatrix (non-trans).
// MPIX=64 for L1 keeps acc regs at 56 -> no spill under 2 CTAs/SM.
// ---------------------------------------------------------------------------
template<int CK, int SECS, int STEPS, int NOUT, int NPAD, int MPIX, int MWARPS,
         int MF, int BPANEL, int BBYTES, bool L1M>
__global__ __launch_bounds__(NTHR, 2) void shift_gemm(
    const __half* __restrict__ ph, const __half* __restrict__ bimg,
    const float* __restrict__ bias, float* __restrict__ out_)
{
    constexpr int NF = NPAD / ((8 / MWARPS) * 8);    // 7 both layers
    constexpr int WM = MF * 16;
    constexpr int WN = NF * 8;
    constexpr int ROWB = MPIX * 2;                   // bytes per k-slot row
    constexpr int NCH  = ROWB / 16;                  // 16B chunks per row
    constexpr int ABYTES = SECS * ROWB;
    constexpr int XT = 256 / MPIX;                   // x-tiles per image row
    constexpr int NTILES = XT * 256 * 8;

    extern __shared__ __align__(16) unsigned char smem[];
    const uint32_t sbA = smem_u32(smem);
    const uint32_t sbB = sbA + ABYTES;
    const int tid = threadIdx.x, wid = tid >> 5, lid = tid & 31;
    const int wm = wid % MWARPS, wn = wid / MWARPS;

    // Copy B image to smem (once)
    for (int i = tid * 16; i < BBYTES; i += NTHR * 16)
        *(uint4*)(smem + ABYTES + i) = *(const uint4*)((const char*)bimg + i);

    // A-fill: cp.async whole tile (shift already baked into the plane)
    auto fill = [&](int t) {
        const int x0 = (t % XT) * MPIX;
        const int y  = (t / XT) & 255;
        const int b  = t / (XT * 256);
        const size_t pbase = (((size_t)b * CK) << 16) + (size_t)y * 256 + x0;
        for (int j = tid; j < SECS * NCH; j += NTHR) {
            const int s = j / NCH, c = j % NCH;
            const __half* src = ph + pbase + (((size_t)s) << 16) + c * 8;
            const uint32_t dst = sbA + s * ROWB + (((c ^ (s & 7)) & (NCH - 1)) << 4);
            const int sz = (s < CK) ? 16 : 0;   // pad k-slots -> zero-fill
            CP_ASYNC16(dst, src, sz);
        }
        CP_COMMIT();
    };

    // ldmatrix lane bases
    const int lg = lid >> 3, lr = lid & 7;
    uint32_t aoff[MF];
    #pragma unroll
    for (int mf = 0; mf < MF; mf++) {
        const int m0 = wm * WM + mf * 16 + (lg & 1) * 8;
        aoff[mf] = sbA + (uint32_t)(((lg >> 1) * 8 + lr) * ROWB)
                 + (uint32_t)((((m0 >> 3) ^ lr) & (NCH - 1)) << 4);
    }
    uint32_t boff[NF / 2], boff2;
    {
        const int nrow = ((lid >> 4) & 1) * 8 + (lid & 7);
        const int kh   = (lid >> 3) & 1;
        #pragma unroll
        for (int p = 0; p < NF / 2; p++)
            boff[p] = sbB + swz(wn * WN + p * 16 + nrow, kh * 8);
        boff2 = sbB + swz(wn * WN + (NF / 2) * 16 + (lid & 7), kh * 8);
    }

    // Prologue: fill first tile
    if ((int)blockIdx.x < NTILES) fill(blockIdx.x);
    CP_WAIT0();
    __syncthreads();

    for (int t = blockIdx.x; t < NTILES; t += GRID) {
        const int x0 = (t % XT) * MPIX;
        const int y  = (t / XT) & 255;
        const int b  = t / (XT * 256);

        // ---- MMA mainloop ----
        float acc[MF][NF][4];
        #pragma unroll
        for (int mf = 0; mf < MF; mf++)
            #pragma unroll
            for (int nf = 0; nf < NF; nf++)
                #pragma unroll
                for (int q = 0; q < 4; q++) acc[mf][nf][q] = 0.0f;

        #pragma unroll 2
        for (int s = 0; s < STEPS; s++) {
            const uint32_t ap = (uint32_t)s * (16 * ROWB);
            const uint32_t bp = (uint32_t)s * BPANEL;

            uint32_t a[MF][4], bf[NF][2];
            #pragma unroll
            for (int mf = 0; mf < MF; mf++) ldsm_x4t(a[mf], aoff[mf] + ap);
            #pragma unroll
            for (int p = 0; p < NF / 2; p++) {
                uint32_t r[4];
                ldsm_x4(r, boff[p] + bp);
                bf[2 * p][0] = r[0]; bf[2 * p][1] = r[1];
                bf[2 * p + 1][0] = r[2]; bf[2 * p + 1][1] = r[3];
            }
            if (NF & 1) ldsm_x2(bf[NF - 1], boff2 + bp);

            #pragma unroll
            for (int mf = 0; mf < MF; mf++)
                #pragma unroll
                for (int nf = 0; nf < NF; nf++)
                    mma_f16(acc[mf][nf], a[mf], bf[nf]);
        }
        __syncthreads();              // all warps done reading A

        // ---- Prefetch next tile's A while epilogue runs ----
        if (t + GRID < NTILES) fill(t + GRID);

        // ---- Epilogue ----
        const int r  = lid >> 2;
        const int ci = lid & 3;
        #pragma unroll
        for (int nf = 0; nf < NF; nf++) {
            const int o0 = wn * WN + nf * 8 + ci * 2;
            if (o0 < NOUT) {
                const float bi0 = __ldg(bias + o0);
                const float bi1 = __ldg(bias + o0 + 1);
                #pragma unroll
                for (int mf = 0; mf < MF; mf++) {
                    const float* d = acc[mf][nf];
                    #pragma unroll
                    for (int q = 0; q < 4; q++) {
                        const int o  = o0 + (q & 1);
                        const int xg = x0 + wm * WM + mf * 16 + r + (q >> 1) * 8;
                        float v = d[q] + ((q & 1) ? bi1 : bi0);
                        if (L1M) {
                            // exact gelu, store fp16 into SHIFTED position
                            v = 0.5f * v * (1.0f + erff(v * 0.70710678118654752440f));
                            const __half hv = __float2half_rn(v);
                            const int g  = o / 40;
                            const int dx = (g == 0) - (g == 1);
                            const int dy = (g == 2) - (g == 3);
                            const int tx = xg - dx, ty = y - dy;
                            const size_t base = ((size_t)(b * 200 + o)) << 16;
                            if ((unsigned)tx < 256u && (unsigned)ty < 256u)
                                g_hs[base + (size_t)ty * 256 + tx] = hv;
                            const bool zx = (dx == 1 && xg == 255) || (dx == -1 && xg == 0);
                            const bool zy = (dy == 1 && y == 255) || (dy == -1 && y == 0);
                            if (zx || zy)
                                g_hs[base + (size_t)y * 256 + xg] = __ushort_as_half(0);
                        } else {
                            out_[(((size_t)(b * NOUT + o)) << 16) + (size_t)y * 256 + xg] = v;
                        }
                    }
                }
            }
        }

        CP_WAIT0();                   // next tile's A landed
        __syncthreads();
    }
}

// L1: MPIX=64  (8192 tiles) warps 2Mx4N, MF=2 -> acc 56 regs (no spill)
// L2: MPIX=128 (4096 tiles) warps 4Mx2N, MF=2 -> acc 56 regs
static constexpr int SMEM1 = 112 * 128 + 50176;   // 14336 + 50176 = 64512
static constexpr int SMEM2 = 208 * 256 + 46592;   // 99840
extern "C" void kernel_launch(void* const* d_in, const int* in_sizes, int n_in,
                              void* d_out, int out_size)
{
    const float* x  = (const float*)d_in[0];
    const float* w1 = (const float*)d_in[1];
    const float* b1 = (const float*)d_in[2];
    const float* w2 = (const float*)d_in[3];
    const float* b2 = (const float*)d_in[4];

    __half *xs, *hs, *w1i, *w2i;
    cudaGetSymbolAddress((void**)&xs, g_xs);
    cudaGetSymbolAddress((void**)&hs, g_hs);
    cudaGetSymbolAddress((void**)&w1i, g_w1i);
    cudaGetSymbolAddress((void**)&w2i, g_w2i);

    auto k1 = shift_gemm<100, 112, 7, 200, 224,  64, 2, 2, 7168, 50176, true >;
    auto k2 = shift_gemm<200, 208, 13, 100, 112, 128, 4, 2, 3584, 46592, false>;
    cudaFuncSetAttribute(k1, cudaFuncAttributeMaxDynamicSharedMemorySize, SMEM1);
    cudaFuncSetAttribute(k2, cudaFuncAttributeMaxDynamicSharedMemorySize, SMEM2);

    prep_x<<<(int)(((size_t)8 * 100 * HW / 4 + NTHR - 1) / NTHR), NTHR>>>(x);
    prep_w<<<64, 256>>>(w1, w2);
    k1<<<GRID, NTHR, SMEM1>>>(xs, w1i, b1, nullptr);
    k2<<<GRID, NTHR, SMEM2>>>(hs, w2i, b2, (float*)d_out);
}